// round 4
// baseline (speedup 1.0000x reference)
#include <cuda_runtime.h>
#include <math.h>

// Problem constants
#define PB 4
#define PS 2048
#define PD 1024
#define PH 16
#define PDH 64
#define PM (PB*PS)          // 8192 rows

// Scratch (device globals — no allocations allowed)
__device__ float g_q[PB*PH*PS*PDH];     // [b*H+h][s][dh]
__device__ float g_k[PB*PH*PS*PDH];
__device__ float g_v[PB*PH*PS*PDH];
__device__ float g_attn[PB*PS*PD];      // [b][s][h*64+c]
__device__ float g_cos[PS*32];
__device__ float g_sin[PS*32];

// ---------------------------------------------------------------------------
// RoPE table: cos/sin(pos * theta^(-2i/64)) computed in fp64 for fidelity
// ---------------------------------------------------------------------------
__global__ void rope_table_kernel(const int* __restrict__ pos) {
    int idx = blockIdx.x * blockDim.x + threadIdx.x;   // 65536 = 2048*32
    int s = idx >> 5;
    int i = idx & 31;
    double p = (double)pos[s];
    double inv = exp(-((double)(2 * i) / 64.0) * log(10000.0));
    double a = p * inv;
    g_cos[idx] = (float)cos(a);
    g_sin[idx] = (float)sin(a);
}

// ---------------------------------------------------------------------------
// QKV GEMM + RoPE epilogue.
// C[m][n] = sum_d x[m][d] * W[n][d],  n in [0,3072) covering q,k,v.
// 128x128 block, BK=16, 256 threads, 8x8 micro-tile per thread.
// Epilogue applies RoPE (for q,k) and scatters into [b*H+h][s][dh] layout.
// ---------------------------------------------------------------------------
__global__ __launch_bounds__(256) void qkv_gemm_rope_kernel(
    const float* __restrict__ x, const float* __restrict__ W)
{
    __shared__ float As[16][132];   // transposed: As[k][m]
    __shared__ float Bs[16][132];   // transposed: Bs[k][n]

    const int tid = threadIdx.x;
    const int tx = tid & 15;
    const int ty = tid >> 4;
    const int bn = blockIdx.x;      // 0..23  (N = 3072)
    const int bm = blockIdx.y;      // 0..63  (M = 8192)

    const float* Abase = x + (size_t)bm * 128 * 1024;
    const float* Wbase = W + (size_t)bn * 128 * 1024;

    float c[8][8];
#pragma unroll
    for (int i = 0; i < 8; i++)
#pragma unroll
        for (int j = 0; j < 8; j++) c[i][j] = 0.0f;

    const int lrow = tid >> 2;      // 0..63
    const int lc4  = tid & 3;       // 0..3

    for (int kt = 0; kt < 64; kt++) {
        const float* ap = Abase + kt * 16 + lc4 * 4;
        const float* wp = Wbase + kt * 16 + lc4 * 4;
        float4 a0 = *(const float4*)(ap + (size_t)lrow * 1024);
        float4 a1 = *(const float4*)(ap + (size_t)(lrow + 64) * 1024);
        float4 b0 = *(const float4*)(wp + (size_t)lrow * 1024);
        float4 b1 = *(const float4*)(wp + (size_t)(lrow + 64) * 1024);
        __syncthreads();
        As[lc4*4+0][lrow] = a0.x; As[lc4*4+1][lrow] = a0.y;
        As[lc4*4+2][lrow] = a0.z; As[lc4*4+3][lrow] = a0.w;
        As[lc4*4+0][lrow+64] = a1.x; As[lc4*4+1][lrow+64] = a1.y;
        As[lc4*4+2][lrow+64] = a1.z; As[lc4*4+3][lrow+64] = a1.w;
        Bs[lc4*4+0][lrow] = b0.x; Bs[lc4*4+1][lrow] = b0.y;
        Bs[lc4*4+2][lrow] = b0.z; Bs[lc4*4+3][lrow] = b0.w;
        Bs[lc4*4+0][lrow+64] = b1.x; Bs[lc4*4+1][lrow+64] = b1.y;
        Bs[lc4*4+2][lrow+64] = b1.z; Bs[lc4*4+3][lrow+64] = b1.w;
        __syncthreads();
#pragma unroll
        for (int k = 0; k < 16; k++) {
            float4 av0 = *(const float4*)&As[k][ty*4];
            float4 av1 = *(const float4*)&As[k][64 + ty*4];
            float4 bv0 = *(const float4*)&Bs[k][tx*4];
            float4 bv1 = *(const float4*)&Bs[k][64 + tx*4];
            float a[8] = {av0.x, av0.y, av0.z, av0.w, av1.x, av1.y, av1.z, av1.w};
            float b[8] = {bv0.x, bv0.y, bv0.z, bv0.w, bv1.x, bv1.y, bv1.z, bv1.w};
#pragma unroll
            for (int i = 0; i < 8; i++)
#pragma unroll
                for (int j = 0; j < 8; j++) c[i][j] += a[i] * b[j];
        }
    }

    // Epilogue: RoPE + scatter. Entire block lies in one of q/k/v (128 | 1024).
    const int kmat = (bn * 128) >> 10;          // 0=q, 1=k, 2=v
    float* dst = (kmat == 0) ? g_q : ((kmat == 1) ? g_k : g_v);
    const int ocol0 = (bn * 128 + tx * 4) & 1023;
    const int ocol1 = (bn * 128 + 64 + tx * 4) & 1023;

#pragma unroll
    for (int i = 0; i < 8; i++) {
        int row = bm * 128 + ((i < 4) ? (ty * 4 + i) : (64 + ty * 4 + i - 4));
        int b = row >> 11;          // /2048
        int s = row & 2047;
#pragma unroll
        for (int g = 0; g < 2; g++) {
            int o = g ? ocol1 : ocol0;
            int h = o >> 6;
            int cc = o & 63;
            float4 v;
            v.x = c[i][g*4+0]; v.y = c[i][g*4+1];
            v.z = c[i][g*4+2]; v.w = c[i][g*4+3];
            if (kmat < 2) {
                int pi = (s << 5) + (cc >> 1);
                float c0 = g_cos[pi],     s0 = g_sin[pi];
                float c1 = g_cos[pi + 1], s1 = g_sin[pi + 1];
                float4 r;
                r.x = v.x * c0 - v.y * s0;
                r.y = v.x * s0 + v.y * c0;
                r.z = v.z * c1 - v.w * s1;
                r.w = v.z * s1 + v.w * c1;
                v = r;
            }
            size_t di = ((size_t)(b * PH + h) * PS + s) * PDH + cc;
            *(float4*)(dst + di) = v;
        }
    }
}

// ---------------------------------------------------------------------------
// Flash attention, fp32. Block = 64 queries of one (b,h); 256 threads (16x16),
// each thread owns a 4x4 score/output micro-tile. Online softmax.
// Smem: Qs,Ks d-major [64][68]; Vs key-major [64][64]; Ps row-major [64][68].
// ---------------------------------------------------------------------------
__global__ __launch_bounds__(256) void flash_attn_kernel() {
    extern __shared__ float sm[];
    float* Qs = sm;                  // 64*68
    float* Ks = sm + 64 * 68;        // 64*68
    float* Vs = Ks + 64 * 68;        // 64*64
    float* Ps = Vs + 64 * 64;        // 64*68

    const int tid = threadIdx.x;
    const int tx = tid & 15;
    const int ty = tid >> 4;
    const int qb = blockIdx.x;       // query block 0..31
    const int bh = blockIdx.y;       // 0..63

    const float* Qg  = g_q + ((size_t)bh * PS + qb * 64) * PDH;
    const float* Kg0 = g_k + (size_t)bh * PS * PDH;
    const float* Vg0 = g_v + (size_t)bh * PS * PDH;

    // Load Q tile transposed (d-major). Strided global read -> conflict-free STS.
    {
        int row = tid & 63;          // query row
        int c4b = tid >> 6;          // 0..3
        float4 t[4];
#pragma unroll
        for (int p = 0; p < 4; p++) {
            int c4 = c4b + p * 4;
            t[p] = *(const float4*)(Qg + row * 64 + c4 * 4);
        }
#pragma unroll
        for (int p = 0; p < 4; p++) {
            int c4 = c4b + p * 4;
            Qs[(c4*4+0)*68 + row] = t[p].x;
            Qs[(c4*4+1)*68 + row] = t[p].y;
            Qs[(c4*4+2)*68 + row] = t[p].z;
            Qs[(c4*4+3)*68 + row] = t[p].w;
        }
    }

    float o[4][4];
    float mrow[4], lrow[4];
#pragma unroll
    for (int i = 0; i < 4; i++) {
        mrow[i] = -1e30f; lrow[i] = 0.0f;
#pragma unroll
        for (int j = 0; j < 4; j++) o[i][j] = 0.0f;
    }

    for (int j = 0; j <= qb; j++) {
        // global reads into regs (before barrier for overlap)
        const float* Kg = Kg0 + j * 64 * 64;
        const float* Vg = Vg0 + j * 64 * 64;
        int row = tid & 63;
        int c4b = tid >> 6;
        float4 kt[4], vt[4];
#pragma unroll
        for (int p = 0; p < 4; p++) {
            int c4 = c4b + p * 4;
            kt[p] = *(const float4*)(Kg + row * 64 + c4 * 4);
            int f = tid + 256 * p;
            vt[p] = *(const float4*)(Vg + (f >> 4) * 64 + (f & 15) * 4);
        }
        __syncthreads();             // prior-iter PV done
#pragma unroll
        for (int p = 0; p < 4; p++) {
            int c4 = c4b + p * 4;
            Ks[(c4*4+0)*68 + row] = kt[p].x;
            Ks[(c4*4+1)*68 + row] = kt[p].y;
            Ks[(c4*4+2)*68 + row] = kt[p].z;
            Ks[(c4*4+3)*68 + row] = kt[p].w;
            int f = tid + 256 * p;
            *(float4*)&Vs[(f >> 4) * 64 + (f & 15) * 4] = vt[p];
        }
        __syncthreads();

        // scores: 4x4 per thread over dh=64
        float sc[4][4];
#pragma unroll
        for (int i = 0; i < 4; i++)
#pragma unroll
            for (int jj = 0; jj < 4; jj++) sc[i][jj] = 0.0f;
#pragma unroll 8
        for (int d = 0; d < 64; d++) {
            float4 q4 = *(const float4*)&Qs[d * 68 + ty * 4];
            float4 k4 = *(const float4*)&Ks[d * 68 + tx * 4];
            float qa[4] = {q4.x, q4.y, q4.z, q4.w};
            float ka[4] = {k4.x, k4.y, k4.z, k4.w};
#pragma unroll
            for (int i = 0; i < 4; i++)
#pragma unroll
                for (int jj = 0; jj < 4; jj++) sc[i][jj] += qa[i] * ka[jj];
        }
        // scale + causal mask
        if (j == qb) {
#pragma unroll
            for (int i = 0; i < 4; i++) {
                int qg = qb * 64 + ty * 4 + i;
#pragma unroll
                for (int jj = 0; jj < 4; jj++) {
                    int kg = j * 64 + tx * 4 + jj;
                    sc[i][jj] = (kg > qg) ? -1e30f : sc[i][jj] * 0.125f;
                }
            }
        } else {
#pragma unroll
            for (int i = 0; i < 4; i++)
#pragma unroll
                for (int jj = 0; jj < 4; jj++) sc[i][jj] *= 0.125f;
        }

        // online softmax update (row reductions across tx via shuffle)
#pragma unroll
        for (int i = 0; i < 4; i++) {
            float rm = fmaxf(fmaxf(sc[i][0], sc[i][1]), fmaxf(sc[i][2], sc[i][3]));
#pragma unroll
            for (int off = 8; off >= 1; off >>= 1)
                rm = fmaxf(rm, __shfl_xor_sync(0xffffffffu, rm, off));
            float mnew = fmaxf(mrow[i], rm);
            float alpha = __expf(mrow[i] - mnew);
            float ps = 0.0f;
#pragma unroll
            for (int jj = 0; jj < 4; jj++) {
                sc[i][jj] = __expf(sc[i][jj] - mnew);
                ps += sc[i][jj];
            }
#pragma unroll
            for (int off = 8; off >= 1; off >>= 1)
                ps += __shfl_xor_sync(0xffffffffu, ps, off);
            lrow[i] = lrow[i] * alpha + ps;
            mrow[i] = mnew;
#pragma unroll
            for (int jj = 0; jj < 4; jj++) o[i][jj] *= alpha;
        }

        // stage P
#pragma unroll
        for (int i = 0; i < 4; i++) {
            float4 pv;
            pv.x = sc[i][0]; pv.y = sc[i][1]; pv.z = sc[i][2]; pv.w = sc[i][3];
            *(float4*)&Ps[(ty * 4 + i) * 68 + tx * 4] = pv;
        }
        __syncthreads();

        // PV accumulate
#pragma unroll 4
        for (int k2 = 0; k2 < 64; k2++) {
            float4 v4 = *(const float4*)&Vs[k2 * 64 + tx * 4];
            float va[4] = {v4.x, v4.y, v4.z, v4.w};
#pragma unroll
            for (int i = 0; i < 4; i++) {
                float p = Ps[(ty * 4 + i) * 68 + k2];
#pragma unroll
                for (int jj = 0; jj < 4; jj++) o[i][jj] += p * va[jj];
            }
        }
    }

    // normalize + write to g_attn [b][s][h*64+c]
    int b = bh >> 4, h = bh & 15;
#pragma unroll
    for (int i = 0; i < 4; i++) {
        int sgl = qb * 64 + ty * 4 + i;
        float inv = 1.0f / lrow[i];
        float4 r;
        r.x = o[i][0] * inv; r.y = o[i][1] * inv;
        r.z = o[i][2] * inv; r.w = o[i][3] * inv;
        *(float4*)(g_attn + ((size_t)(b * PS + sgl) * PD) + h * 64 + tx * 4) = r;
    }
}

// ---------------------------------------------------------------------------
// Output projection: out[m][n] = sum_d g_attn[m][d] * W_o[n][d]
// NOTE: g_attn is referenced directly from device code (a __device__ symbol
// must NOT be passed as a host-side kernel argument).
// ---------------------------------------------------------------------------
__global__ __launch_bounds__(256) void out_gemm_kernel(
    const float* __restrict__ W, float* __restrict__ C)
{
    __shared__ float As[16][132];
    __shared__ float Bs[16][132];

    const int tid = threadIdx.x;
    const int tx = tid & 15;
    const int ty = tid >> 4;
    const int bn = blockIdx.x;      // 0..7
    const int bm = blockIdx.y;      // 0..63

    const float* Abase = g_attn + (size_t)bm * 128 * 1024;
    const float* Wbase = W + (size_t)bn * 128 * 1024;

    float c[8][8];
#pragma unroll
    for (int i = 0; i < 8; i++)
#pragma unroll
        for (int j = 0; j < 8; j++) c[i][j] = 0.0f;

    const int lrow = tid >> 2;
    const int lc4  = tid & 3;

    for (int kt = 0; kt < 64; kt++) {
        const float* ap = Abase + kt * 16 + lc4 * 4;
        const float* wp = Wbase + kt * 16 + lc4 * 4;
        float4 a0 = *(const float4*)(ap + (size_t)lrow * 1024);
        float4 a1 = *(const float4*)(ap + (size_t)(lrow + 64) * 1024);
        float4 b0 = *(const float4*)(wp + (size_t)lrow * 1024);
        float4 b1 = *(const float4*)(wp + (size_t)(lrow + 64) * 1024);
        __syncthreads();
        As[lc4*4+0][lrow] = a0.x; As[lc4*4+1][lrow] = a0.y;
        As[lc4*4+2][lrow] = a0.z; As[lc4*4+3][lrow] = a0.w;
        As[lc4*4+0][lrow+64] = a1.x; As[lc4*4+1][lrow+64] = a1.y;
        As[lc4*4+2][lrow+64] = a1.z; As[lc4*4+3][lrow+64] = a1.w;
        Bs[lc4*4+0][lrow] = b0.x; Bs[lc4*4+1][lrow] = b0.y;
        Bs[lc4*4+2][lrow] = b0.z; Bs[lc4*4+3][lrow] = b0.w;
        Bs[lc4*4+0][lrow+64] = b1.x; Bs[lc4*4+1][lrow+64] = b1.y;
        Bs[lc4*4+2][lrow+64] = b1.z; Bs[lc4*4+3][lrow+64] = b1.w;
        __syncthreads();
#pragma unroll
        for (int k = 0; k < 16; k++) {
            float4 av0 = *(const float4*)&As[k][ty*4];
            float4 av1 = *(const float4*)&As[k][64 + ty*4];
            float4 bv0 = *(const float4*)&Bs[k][tx*4];
            float4 bv1 = *(const float4*)&Bs[k][64 + tx*4];
            float a[8] = {av0.x, av0.y, av0.z, av0.w, av1.x, av1.y, av1.z, av1.w};
            float b[8] = {bv0.x, bv0.y, bv0.z, bv0.w, bv1.x, bv1.y, bv1.z, bv1.w};
#pragma unroll
            for (int i = 0; i < 8; i++)
#pragma unroll
                for (int j = 0; j < 8; j++) c[i][j] += a[i] * b[j];
        }
    }

#pragma unroll
    for (int i = 0; i < 8; i++) {
        int row = bm * 128 + ((i < 4) ? (ty * 4 + i) : (64 + ty * 4 + i - 4));
        float4 v0, v1;
        v0.x = c[i][0]; v0.y = c[i][1]; v0.z = c[i][2]; v0.w = c[i][3];
        v1.x = c[i][4]; v1.y = c[i][5]; v1.z = c[i][6]; v1.w = c[i][7];
        *(float4*)(C + (size_t)row * 1024 + bn * 128 + tx * 4)      = v0;
        *(float4*)(C + (size_t)row * 1024 + bn * 128 + 64 + tx * 4) = v1;
    }
}

// ---------------------------------------------------------------------------
extern "C" void kernel_launch(void* const* d_in, const int* in_sizes, int n_in,
                              void* d_out, int out_size) {
    const float* x     = (const float*)d_in[0];
    const float* W_qkv = (const float*)d_in[1];
    const float* W_o   = (const float*)d_in[2];
    const int*   tpos  = (const int*)d_in[3];
    float* out = (float*)d_out;

    // Flash attention needs 68608 B of dynamic smem (> 48KB default)
    static const size_t FLASH_SMEM = (size_t)(64*68*2 + 64*64 + 64*68) * sizeof(float);
    cudaFuncSetAttribute(flash_attn_kernel,
                         cudaFuncAttributeMaxDynamicSharedMemorySize,
                         (int)FLASH_SMEM);

    rope_table_kernel<<<64, 1024>>>(tpos);
    qkv_gemm_rope_kernel<<<dim3(24, 64), 256>>>(x, W_qkv);
    flash_attn_kernel<<<dim3(32, 64), 256, FLASH_SMEM>>>();
    out_gemm_kernel<<<dim3(8, 64), 256>>>(W_o, out);
}

// round 7
// speedup vs baseline: 1.3638x; 1.3638x over previous
#include <cuda_runtime.h>
#include <cuda_bf16.h>
#include <math.h>
#include <stdint.h>

// Problem constants
#define PB 4
#define PS 2048
#define PD 1024
#define PH 16
#define PDH 64

// ---------------------------------------------------------------------------
// Scratch (device globals — no allocations allowed)
// ---------------------------------------------------------------------------
__device__ float g_q[PB*PH*PS*PDH];     // [b*H+h][s][dh]
__device__ float g_k[PB*PH*PS*PDH];
__device__ float g_v[PB*PH*PS*PDH];
__device__ float g_attn[PB*PS*PD];      // [b][s][h*64+c]
__device__ float g_cos[PS*32];
__device__ float g_sin[PS*32];

// bf16 split operands for tensor-core GEMMs
__device__ __nv_bfloat16 g_xh[8192*1024], g_xl[8192*1024];      // x
__device__ __nv_bfloat16 g_wqh[3072*1024], g_wql[3072*1024];    // W_qkv
__device__ __nv_bfloat16 g_woh[1024*1024], g_wol[1024*1024];    // W_o
__device__ __nv_bfloat16 g_ah[8192*1024], g_al[8192*1024];      // attn out

// ---------------------------------------------------------------------------
// Portable PTX helpers (NO arch-specific 'a' features — toolchain targets
// compute_103 base, which rejects tcgen05/TMEM)
// ---------------------------------------------------------------------------
__device__ __forceinline__ uint32_t smem_u32(const void* p) {
    uint32_t a;
    asm("{ .reg .u64 t; cvta.to.shared.u64 t, %1; cvt.u32.u64 %0, t; }"
        : "=r"(a) : "l"(p));
    return a;
}

__device__ __forceinline__ void cp16(uint32_t saddr, const void* gaddr) {
    asm volatile("cp.async.cg.shared.global [%0], [%1], 16;"
                 :: "r"(saddr), "l"(gaddr) : "memory");
}
#define CP_COMMIT() asm volatile("cp.async.commit_group;" ::: "memory")
#define CP_WAIT0()  asm volatile("cp.async.wait_group 0;" ::: "memory")

__device__ __forceinline__ void ldm_x4(uint32_t* r, uint32_t addr) {
    asm volatile("ldmatrix.sync.aligned.m8n8.x4.shared.b16 {%0,%1,%2,%3}, [%4];"
        : "=r"(r[0]), "=r"(r[1]), "=r"(r[2]), "=r"(r[3]) : "r"(addr));
}

__device__ __forceinline__ void mma16816(float* d, const uint32_t* a, const uint32_t* b) {
    asm volatile(
        "mma.sync.aligned.m16n8k16.row.col.f32.bf16.bf16.f32 "
        "{%0,%1,%2,%3}, {%4,%5,%6,%7}, {%8,%9}, {%0,%1,%2,%3};"
        : "+f"(d[0]), "+f"(d[1]), "+f"(d[2]), "+f"(d[3])
        : "r"(a[0]), "r"(a[1]), "r"(a[2]), "r"(a[3]), "r"(b[0]), "r"(b[1]));
}

// ---------------------------------------------------------------------------
// RoPE table (fp64 for fidelity)
// ---------------------------------------------------------------------------
__global__ void rope_table_kernel(const int* __restrict__ pos) {
    int idx = blockIdx.x * blockDim.x + threadIdx.x;   // 65536
    int s = idx >> 5;
    int i = idx & 31;
    double p = (double)pos[s];
    double inv = exp(-((double)(2 * i) / 64.0) * log(10000.0));
    double a = p * inv;
    g_cos[idx] = (float)cos(a);
    g_sin[idx] = (float)sin(a);
}

// ---------------------------------------------------------------------------
// fp32 -> bf16 hi/lo split (2-term); 4 elems/thread
// ---------------------------------------------------------------------------
__device__ __forceinline__ void split4(const float* __restrict__ src,
                                       __nv_bfloat16* __restrict__ hi,
                                       __nv_bfloat16* __restrict__ lo) {
    int i = blockIdx.x * blockDim.x + threadIdx.x;
    float4 v = ((const float4*)src)[i];
    __nv_bfloat16 h0 = __float2bfloat16(v.x);
    __nv_bfloat16 h1 = __float2bfloat16(v.y);
    __nv_bfloat16 h2 = __float2bfloat16(v.z);
    __nv_bfloat16 h3 = __float2bfloat16(v.w);
    __nv_bfloat16 l0 = __float2bfloat16(v.x - __bfloat162float(h0));
    __nv_bfloat16 l1 = __float2bfloat16(v.y - __bfloat162float(h1));
    __nv_bfloat16 l2 = __float2bfloat16(v.z - __bfloat162float(h2));
    __nv_bfloat16 l3 = __float2bfloat16(v.w - __bfloat162float(h3));
    ((__nv_bfloat162*)hi)[i*2]   = __halves2bfloat162(h0, h1);
    ((__nv_bfloat162*)hi)[i*2+1] = __halves2bfloat162(h2, h3);
    ((__nv_bfloat162*)lo)[i*2]   = __halves2bfloat162(l0, l1);
    ((__nv_bfloat162*)lo)[i*2+1] = __halves2bfloat162(l2, l3);
}

__global__ void split_x_kernel(const float* __restrict__ x)  { split4(x, g_xh, g_xl); }
__global__ void split_wq_kernel(const float* __restrict__ w) { split4(w, g_wqh, g_wql); }
__global__ void split_wo_kernel(const float* __restrict__ w) { split4(w, g_woh, g_wol); }
__global__ void split_attn_kernel()                          { split4(g_attn, g_ah, g_al); }

// ---------------------------------------------------------------------------
// mma.sync bf16 GEMM, 128x128 CTA tile, BK=32, 256 threads.
// C[m][n] = sum_k A[m][k]*B[n][k], 3-term split: AhBh + AhBl + AlBh, fp32 acc.
// Warp tile 64x32 (warp grid 2m x 4n); per warp per k16: 4x4 m16n8k16 x3.
// MODE 0: A=x, B=W_qkv, epilogue RoPE+scatter into g_q/g_k/g_v.
// MODE 1: A=attn, B=W_o, epilogue plain store into Cout.
// ---------------------------------------------------------------------------
#define LDT 40   // smem row stride (bf16 elems); 80B rows -> conflict-free ldmatrix

template<int MODE>
__global__ __launch_bounds__(256)
void mma_gemm_kernel(float* __restrict__ Cout)
{
    const __nv_bfloat16 *Ahp, *Alp, *Bhp, *Blp;
    if (MODE == 0) { Ahp = g_xh; Alp = g_xl; Bhp = g_wqh; Blp = g_wql; }
    else           { Ahp = g_ah; Alp = g_al; Bhp = g_woh; Blp = g_wol; }

    __shared__ __align__(16) __nv_bfloat16 sAh[128*LDT], sAl[128*LDT];
    __shared__ __align__(16) __nv_bfloat16 sBh[128*LDT], sBl[128*LDT];

    const int tid = threadIdx.x;
    const int n0 = blockIdx.x * 128;
    const int m0 = blockIdx.y * 128;
    const int lane = tid & 31, w = tid >> 5;
    const int wm = w >> 2, wn = w & 3;

    // gmem -> smem mapping: thread covers row lr, cols [lh*16, lh*16+16)
    const int lr = tid >> 1, lh = tid & 1;
    const __nv_bfloat16* gAh = Ahp + (size_t)(m0 + lr) * 1024 + lh * 16;
    const __nv_bfloat16* gAl = Alp + (size_t)(m0 + lr) * 1024 + lh * 16;
    const __nv_bfloat16* gBh = Bhp + (size_t)(n0 + lr) * 1024 + lh * 16;
    const __nv_bfloat16* gBl = Blp + (size_t)(n0 + lr) * 1024 + lh * 16;
    const uint32_t sOff = (uint32_t)((lr * LDT + lh * 16) * 2);
    const uint32_t sAhB = smem_u32(sAh), sAlB = smem_u32(sAl);
    const uint32_t sBhB = smem_u32(sBh), sBlB = smem_u32(sBl);

    // ldmatrix per-thread base offsets
    const int quad = lane >> 3, qi = lane & 7;
    const uint32_t aoff = (uint32_t)(((wm*64 + (quad&1)*8 + qi) * LDT + (quad>>1)*8) * 2);
    const uint32_t boff = (uint32_t)(((wn*32 + (quad>>1)*8 + qi) * LDT + (quad&1)*8) * 2);

    float acc[4][4][4];
#pragma unroll
    for (int a = 0; a < 4; a++)
#pragma unroll
        for (int b = 0; b < 4; b++)
#pragma unroll
            for (int c = 0; c < 4; c++) acc[a][b][c] = 0.0f;

    for (int kt = 0; kt < 32; kt++) {
        __syncthreads();                       // previous compute done
        const int kb = kt * 32;
        cp16(sAhB + sOff,      gAh + kb);  cp16(sAhB + sOff + 16, gAh + kb + 8);
        cp16(sAlB + sOff,      gAl + kb);  cp16(sAlB + sOff + 16, gAl + kb + 8);
        cp16(sBhB + sOff,      gBh + kb);  cp16(sBhB + sOff + 16, gBh + kb + 8);
        cp16(sBlB + sOff,      gBl + kb);  cp16(sBlB + sOff + 16, gBl + kb + 8);
        CP_COMMIT(); CP_WAIT0();
        __syncthreads();

#pragma unroll
        for (int ks = 0; ks < 2; ks++) {
            const uint32_t kso = ks * 32;      // 16 bf16 cols * 2B
            uint32_t aH[4][4], aL[4][4], bH[2][4], bL[2][4];
#pragma unroll
            for (int mt = 0; mt < 4; mt++) {
                ldm_x4(aH[mt], sAhB + aoff + mt * (16*LDT*2) + kso);
                ldm_x4(aL[mt], sAlB + aoff + mt * (16*LDT*2) + kso);
            }
#pragma unroll
            for (int np = 0; np < 2; np++) {
                ldm_x4(bH[np], sBhB + boff + np * (16*LDT*2) + kso);
                ldm_x4(bL[np], sBlB + boff + np * (16*LDT*2) + kso);
            }
#pragma unroll
            for (int mt = 0; mt < 4; mt++)
#pragma unroll
                for (int nt = 0; nt < 4; nt++) {
                    const uint32_t* ph = &bH[nt >> 1][(nt & 1) * 2];
                    const uint32_t* pl = &bL[nt >> 1][(nt & 1) * 2];
                    mma16816(acc[mt][nt], aH[mt], ph);
                    mma16816(acc[mt][nt], aH[mt], pl);
                    mma16816(acc[mt][nt], aL[mt], ph);
                }
        }
    }

    // Epilogue. C frag: d0,d1 -> row g, cols 2tig,2tig+1; d2,d3 -> row g+8.
    const int g = lane >> 2, tig = lane & 3;
    if (MODE == 0) {
        const int kmat = n0 >> 10;                   // 0=q 1=k 2=v
        float* dst = (kmat == 0) ? g_q : ((kmat == 1) ? g_k : g_v);
#pragma unroll
        for (int mt = 0; mt < 4; mt++)
#pragma unroll
            for (int hh = 0; hh < 2; hh++) {
                const int m = m0 + wm*64 + mt*16 + hh*8 + g;
                const int b = m >> 11, s = m & 2047;
#pragma unroll
                for (int nt = 0; nt < 4; nt++) {
                    const int colg = n0 + wn*32 + nt*8 + 2*tig;
                    const int h = (colg >> 6) & 15;
                    const int cc = colg & 63;
                    const float v0 = acc[mt][nt][hh*2];
                    const float v1 = acc[mt][nt][hh*2 + 1];
                    float2 r;
                    if (kmat < 2) {
                        const int pi = (s << 5) + (cc >> 1);
                        const float c_ = g_cos[pi], s_ = g_sin[pi];
                        r.x = v0 * c_ - v1 * s_;
                        r.y = v0 * s_ + v1 * c_;
                    } else {
                        r.x = v0; r.y = v1;
                    }
                    *(float2*)(dst + ((size_t)((b*PH + h)*PS + s))*PDH + cc) = r;
                }
            }
    } else {
#pragma unroll
        for (int mt = 0; mt < 4; mt++)
#pragma unroll
            for (int hh = 0; hh < 2; hh++) {
                const int m = m0 + wm*64 + mt*16 + hh*8 + g;
#pragma unroll
                for (int nt = 0; nt < 4; nt++) {
                    const int colg = n0 + wn*32 + nt*8 + 2*tig;
                    float2 r;
                    r.x = acc[mt][nt][hh*2];
                    r.y = acc[mt][nt][hh*2 + 1];
                    *(float2*)(Cout + (size_t)m * 1024 + colg) = r;
                }
            }
    }
}

// ---------------------------------------------------------------------------
// Flash attention, fp32 (unchanged from passing round)
// ---------------------------------------------------------------------------
__global__ __launch_bounds__(256) void flash_attn_kernel() {
    extern __shared__ float sm[];
    float* Qs = sm;                  // 64*68
    float* Ks = sm + 64 * 68;        // 64*68
    float* Vs = Ks + 64 * 68;        // 64*64
    float* Ps = Vs + 64 * 64;        // 64*68

    const int tid = threadIdx.x;
    const int tx = tid & 15;
    const int ty = tid >> 4;
    const int qb = blockIdx.x;
    const int bh = blockIdx.y;

    const float* Qg  = g_q + ((size_t)bh * PS + qb * 64) * PDH;
    const float* Kg0 = g_k + (size_t)bh * PS * PDH;
    const float* Vg0 = g_v + (size_t)bh * PS * PDH;

    {
        int row = tid & 63;
        int c4b = tid >> 6;
        float4 t[4];
#pragma unroll
        for (int p = 0; p < 4; p++) {
            int c4 = c4b + p * 4;
            t[p] = *(const float4*)(Qg + row * 64 + c4 * 4);
        }
#pragma unroll
        for (int p = 0; p < 4; p++) {
            int c4 = c4b + p * 4;
            Qs[(c4*4+0)*68 + row] = t[p].x;
            Qs[(c4*4+1)*68 + row] = t[p].y;
            Qs[(c4*4+2)*68 + row] = t[p].z;
            Qs[(c4*4+3)*68 + row] = t[p].w;
        }
    }

    float o[4][4];
    float mrow[4], lrow[4];
#pragma unroll
    for (int i = 0; i < 4; i++) {
        mrow[i] = -1e30f; lrow[i] = 0.0f;
#pragma unroll
        for (int j = 0; j < 4; j++) o[i][j] = 0.0f;
    }

    for (int j = 0; j <= qb; j++) {
        const float* Kg = Kg0 + j * 64 * 64;
        const float* Vg = Vg0 + j * 64 * 64;
        int row = tid & 63;
        int c4b = tid >> 6;
        float4 kt[4], vt[4];
#pragma unroll
        for (int p = 0; p < 4; p++) {
            int c4 = c4b + p * 4;
            kt[p] = *(const float4*)(Kg + row * 64 + c4 * 4);
            int f = tid + 256 * p;
            vt[p] = *(const float4*)(Vg + (f >> 4) * 64 + (f & 15) * 4);
        }
        __syncthreads();
#pragma unroll
        for (int p = 0; p < 4; p++) {
            int c4 = c4b + p * 4;
            Ks[(c4*4+0)*68 + row] = kt[p].x;
            Ks[(c4*4+1)*68 + row] = kt[p].y;
            Ks[(c4*4+2)*68 + row] = kt[p].z;
            Ks[(c4*4+3)*68 + row] = kt[p].w;
            int f = tid + 256 * p;
            *(float4*)&Vs[(f >> 4) * 64 + (f & 15) * 4] = vt[p];
        }
        __syncthreads();

        float sc[4][4];
#pragma unroll
        for (int i = 0; i < 4; i++)
#pragma unroll
            for (int jj = 0; jj < 4; jj++) sc[i][jj] = 0.0f;
#pragma unroll 8
        for (int d = 0; d < 64; d++) {
            float4 q4 = *(const float4*)&Qs[d * 68 + ty * 4];
            float4 k4 = *(const float4*)&Ks[d * 68 + tx * 4];
            float qa[4] = {q4.x, q4.y, q4.z, q4.w};
            float ka[4] = {k4.x, k4.y, k4.z, k4.w};
#pragma unroll
            for (int i = 0; i < 4; i++)
#pragma unroll
                for (int jj = 0; jj < 4; jj++) sc[i][jj] += qa[i] * ka[jj];
        }
        if (j == qb) {
#pragma unroll
            for (int i = 0; i < 4; i++) {
                int qg = qb * 64 + ty * 4 + i;
#pragma unroll
                for (int jj = 0; jj < 4; jj++) {
                    int kg = j * 64 + tx * 4 + jj;
                    sc[i][jj] = (kg > qg) ? -1e30f : sc[i][jj] * 0.125f;
                }
            }
        } else {
#pragma unroll
            for (int i = 0; i < 4; i++)
#pragma unroll
                for (int jj = 0; jj < 4; jj++) sc[i][jj] *= 0.125f;
        }

#pragma unroll
        for (int i = 0; i < 4; i++) {
            float rm = fmaxf(fmaxf(sc[i][0], sc[i][1]), fmaxf(sc[i][2], sc[i][3]));
#pragma unroll
            for (int off = 8; off >= 1; off >>= 1)
                rm = fmaxf(rm, __shfl_xor_sync(0xffffffffu, rm, off));
            float mnew = fmaxf(mrow[i], rm);
            float alpha = __expf(mrow[i] - mnew);
            float ps = 0.0f;
#pragma unroll
            for (int jj = 0; jj < 4; jj++) {
                sc[i][jj] = __expf(sc[i][jj] - mnew);
                ps += sc[i][jj];
            }
#pragma unroll
            for (int off = 8; off >= 1; off >>= 1)
                ps += __shfl_xor_sync(0xffffffffu, ps, off);
            lrow[i] = lrow[i] * alpha + ps;
            mrow[i] = mnew;
#pragma unroll
            for (int jj = 0; jj < 4; jj++) o[i][jj] *= alpha;
        }

#pragma unroll
        for (int i = 0; i < 4; i++) {
            float4 pv;
            pv.x = sc[i][0]; pv.y = sc[i][1]; pv.z = sc[i][2]; pv.w = sc[i][3];
            *(float4*)&Ps[(ty * 4 + i) * 68 + tx * 4] = pv;
        }
        __syncthreads();

#pragma unroll 4
        for (int k2 = 0; k2 < 64; k2++) {
            float4 v4 = *(const float4*)&Vs[k2 * 64 + tx * 4];
            float va[4] = {v4.x, v4.y, v4.z, v4.w};
#pragma unroll
            for (int i = 0; i < 4; i++) {
                float p = Ps[(ty * 4 + i) * 68 + k2];
#pragma unroll
                for (int jj = 0; jj < 4; jj++) o[i][jj] += p * va[jj];
            }
        }
    }

    int b = bh >> 4, h = bh & 15;
#pragma unroll
    for (int i = 0; i < 4; i++) {
        int sgl = qb * 64 + ty * 4 + i;
        float inv = 1.0f / lrow[i];
        float4 r;
        r.x = o[i][0] * inv; r.y = o[i][1] * inv;
        r.z = o[i][2] * inv; r.w = o[i][3] * inv;
        *(float4*)(g_attn + ((size_t)(b * PS + sgl) * PD) + h * 64 + tx * 4) = r;
    }
}

// ---------------------------------------------------------------------------
extern "C" void kernel_launch(void* const* d_in, const int* in_sizes, int n_in,
                              void* d_out, int out_size) {
    const float* x     = (const float*)d_in[0];
    const float* W_qkv = (const float*)d_in[1];
    const float* W_o   = (const float*)d_in[2];
    const int*   tpos  = (const int*)d_in[3];
    float* out = (float*)d_out;

    static const size_t FLASH_SMEM = (size_t)(64*68*2 + 64*64 + 64*68) * sizeof(float);
    cudaFuncSetAttribute(flash_attn_kernel,
                         cudaFuncAttributeMaxDynamicSharedMemorySize, (int)FLASH_SMEM);

    rope_table_kernel<<<64, 1024>>>(tpos);
    split_x_kernel<<<8192, 256>>>(x);
    split_wq_kernel<<<3072, 256>>>(W_qkv);
    split_wo_kernel<<<1024, 256>>>(W_o);

    mma_gemm_kernel<0><<<dim3(24, 64), 256>>>(nullptr);   // QKV + RoPE
    flash_attn_kernel<<<dim3(32, 64), 256, FLASH_SMEM>>>();
    split_attn_kernel<<<8192, 256>>>();
    mma_gemm_kernel<1><<<dim3(8, 64), 256>>>(out);        // out proj
}

// round 8
// speedup vs baseline: 1.4081x; 1.0325x over previous
#include <cuda_runtime.h>
#include <cuda_bf16.h>
#include <math.h>
#include <stdint.h>

// Problem constants
#define PB 4
#define PS 2048
#define PD 1024
#define PH 16
#define PDH 64

// ---------------------------------------------------------------------------
// Scratch (device globals — no allocations allowed)
// ---------------------------------------------------------------------------
__device__ float g_q[PB*PH*PS*PDH];     // [b*H+h][s][dh]
__device__ float g_k[PB*PH*PS*PDH];
__device__ float g_v[PB*PH*PS*PDH];
__device__ float g_attn[PB*PS*PD];      // [b][s][h*64+c]
__device__ float g_cos[PS*32];
__device__ float g_sin[PS*32];

// bf16 split operands for tensor-core GEMMs
__device__ __nv_bfloat16 g_xh[8192*1024], g_xl[8192*1024];      // x
__device__ __nv_bfloat16 g_wqh[3072*1024], g_wql[3072*1024];    // W_qkv
__device__ __nv_bfloat16 g_woh[1024*1024], g_wol[1024*1024];    // W_o
__device__ __nv_bfloat16 g_ah[8192*1024], g_al[8192*1024];      // attn out

// ---------------------------------------------------------------------------
// Portable PTX helpers (toolchain targets base compute_103: no tcgen05/TMEM)
// ---------------------------------------------------------------------------
__device__ __forceinline__ uint32_t smem_u32(const void* p) {
    uint32_t a;
    asm("{ .reg .u64 t; cvta.to.shared.u64 t, %1; cvt.u32.u64 %0, t; }"
        : "=r"(a) : "l"(p));
    return a;
}

__device__ __forceinline__ void cp16(uint32_t saddr, const void* gaddr) {
    asm volatile("cp.async.cg.shared.global [%0], [%1], 16;"
                 :: "r"(saddr), "l"(gaddr) : "memory");
}
#define CP_COMMIT() asm volatile("cp.async.commit_group;" ::: "memory")
#define CP_WAIT0()  asm volatile("cp.async.wait_group 0;" ::: "memory")
#define CP_WAIT1()  asm volatile("cp.async.wait_group 1;" ::: "memory")

__device__ __forceinline__ void ldm_x4(uint32_t* r, uint32_t addr) {
    asm volatile("ldmatrix.sync.aligned.m8n8.x4.shared.b16 {%0,%1,%2,%3}, [%4];"
        : "=r"(r[0]), "=r"(r[1]), "=r"(r[2]), "=r"(r[3]) : "r"(addr));
}

__device__ __forceinline__ void mma16816(float* d, const uint32_t* a, const uint32_t* b) {
    asm volatile(
        "mma.sync.aligned.m16n8k16.row.col.f32.bf16.bf16.f32 "
        "{%0,%1,%2,%3}, {%4,%5,%6,%7}, {%8,%9}, {%0,%1,%2,%3};"
        : "+f"(d[0]), "+f"(d[1]), "+f"(d[2]), "+f"(d[3])
        : "r"(a[0]), "r"(a[1]), "r"(a[2]), "r"(a[3]), "r"(b[0]), "r"(b[1]));
}

// ---------------------------------------------------------------------------
// RoPE table (fp64 for fidelity)
// ---------------------------------------------------------------------------
__global__ void rope_table_kernel(const int* __restrict__ pos) {
    int idx = blockIdx.x * blockDim.x + threadIdx.x;   // 65536
    int s = idx >> 5;
    int i = idx & 31;
    double p = (double)pos[s];
    double inv = exp(-((double)(2 * i) / 64.0) * log(10000.0));
    double a = p * inv;
    g_cos[idx] = (float)cos(a);
    g_sin[idx] = (float)sin(a);
}

// ---------------------------------------------------------------------------
// fp32 -> bf16 hi/lo split (2-term); 4 elems/thread
// ---------------------------------------------------------------------------
__device__ __forceinline__ void split4(const float* __restrict__ src,
                                       __nv_bfloat16* __restrict__ hi,
                                       __nv_bfloat16* __restrict__ lo) {
    int i = blockIdx.x * blockDim.x + threadIdx.x;
    float4 v = ((const float4*)src)[i];
    __nv_bfloat16 h0 = __float2bfloat16(v.x);
    __nv_bfloat16 h1 = __float2bfloat16(v.y);
    __nv_bfloat16 h2 = __float2bfloat16(v.z);
    __nv_bfloat16 h3 = __float2bfloat16(v.w);
    __nv_bfloat16 l0 = __float2bfloat16(v.x - __bfloat162float(h0));
    __nv_bfloat16 l1 = __float2bfloat16(v.y - __bfloat162float(h1));
    __nv_bfloat16 l2 = __float2bfloat16(v.z - __bfloat162float(h2));
    __nv_bfloat16 l3 = __float2bfloat16(v.w - __bfloat162float(h3));
    ((__nv_bfloat162*)hi)[i*2]   = __halves2bfloat162(h0, h1);
    ((__nv_bfloat162*)hi)[i*2+1] = __halves2bfloat162(h2, h3);
    ((__nv_bfloat162*)lo)[i*2]   = __halves2bfloat162(l0, l1);
    ((__nv_bfloat162*)lo)[i*2+1] = __halves2bfloat162(l2, l3);
}

__global__ void split_x_kernel(const float* __restrict__ x)  { split4(x, g_xh, g_xl); }
__global__ void split_wq_kernel(const float* __restrict__ w) { split4(w, g_wqh, g_wql); }
__global__ void split_wo_kernel(const float* __restrict__ w) { split4(w, g_woh, g_wol); }
__global__ void split_attn_kernel()                          { split4(g_attn, g_ah, g_al); }

// ---------------------------------------------------------------------------
// mma.sync bf16 GEMM, 128x128 CTA tile, BK=32, 256 threads,
// 2-stage cp.async pipeline (double-buffered smem, 80 KB dynamic).
// C[m][n] = sum_k A[m][k]*B[n][k], 3-term split: AhBh + AhBl + AlBh, fp32 acc.
// MODE 0: A=x, B=W_qkv, epilogue RoPE+scatter into g_q/g_k/g_v.
// MODE 1: A=attn, B=W_o, epilogue plain store into Cout.
// ---------------------------------------------------------------------------
#define LDT 40            // smem row stride (bf16); 80B rows -> conflict-free ldmatrix
#define TILE_B (128*LDT*2)        // 10240 B per tile
#define STAGE_B (4*TILE_B)        // Ah,Al,Bh,Bl per stage = 40960 B
#define GEMM_SMEM (2*STAGE_B)     // 81920 B

template<int MODE>
__global__ __launch_bounds__(256)
void mma_gemm_kernel(float* __restrict__ Cout)
{
    const __nv_bfloat16 *Ahp, *Alp, *Bhp, *Blp;
    if (MODE == 0) { Ahp = g_xh; Alp = g_xl; Bhp = g_wqh; Blp = g_wql; }
    else           { Ahp = g_ah; Alp = g_al; Bhp = g_woh; Blp = g_wol; }

    extern __shared__ char dsm[];
    const uint32_t sBase = smem_u32(dsm);

    const int tid = threadIdx.x;
    const int n0 = blockIdx.x * 128;
    const int m0 = blockIdx.y * 128;
    const int lane = tid & 31, w = tid >> 5;
    const int wm = w >> 2, wn = w & 3;

    // gmem -> smem mapping: thread covers row lr, cols [lh*16, lh*16+16)
    const int lr = tid >> 1, lh = tid & 1;
    const __nv_bfloat16* gAh = Ahp + (size_t)(m0 + lr) * 1024 + lh * 16;
    const __nv_bfloat16* gAl = Alp + (size_t)(m0 + lr) * 1024 + lh * 16;
    const __nv_bfloat16* gBh = Bhp + (size_t)(n0 + lr) * 1024 + lh * 16;
    const __nv_bfloat16* gBl = Blp + (size_t)(n0 + lr) * 1024 + lh * 16;
    const uint32_t sOff = (uint32_t)((lr * LDT + lh * 16) * 2);

    // ldmatrix per-thread base offsets
    const int quad = lane >> 3, qi = lane & 7;
    const uint32_t aoff = (uint32_t)(((wm*64 + (quad&1)*8 + qi) * LDT + (quad>>1)*8) * 2);
    const uint32_t boff = (uint32_t)(((wn*32 + (quad>>1)*8 + qi) * LDT + (quad&1)*8) * 2);

    float acc[4][4][4];
#pragma unroll
    for (int a = 0; a < 4; a++)
#pragma unroll
        for (int b = 0; b < 4; b++)
#pragma unroll
            for (int c = 0; c < 4; c++) acc[a][b][c] = 0.0f;

    // stage loader
    auto load_stage = [&](int kt, int stg) {
        const int kb = kt * 32;
        const uint32_t s0 = sBase + stg * STAGE_B + sOff;
        cp16(s0,                    gAh + kb);  cp16(s0 + 16,              gAh + kb + 8);
        cp16(s0 + TILE_B,           gAl + kb);  cp16(s0 + TILE_B + 16,     gAl + kb + 8);
        cp16(s0 + 2*TILE_B,         gBh + kb);  cp16(s0 + 2*TILE_B + 16,   gBh + kb + 8);
        cp16(s0 + 3*TILE_B,         gBl + kb);  cp16(s0 + 3*TILE_B + 16,   gBl + kb + 8);
        CP_COMMIT();
    };

    load_stage(0, 0);

    for (int kt = 0; kt < 32; kt++) {
        const int stg = kt & 1;
        if (kt + 1 < 32) {
            load_stage(kt + 1, stg ^ 1);   // prev compute on stg^1 finished (trailing barrier)
            CP_WAIT1();                    // stage kt complete; kt+1 may be in flight
        } else {
            CP_WAIT0();
        }
        __syncthreads();

        const uint32_t sAhB = sBase + stg * STAGE_B;
        const uint32_t sAlB = sAhB + TILE_B;
        const uint32_t sBhB = sAhB + 2*TILE_B;
        const uint32_t sBlB = sAhB + 3*TILE_B;

#pragma unroll
        for (int ks = 0; ks < 2; ks++) {
            const uint32_t kso = ks * 32;      // 16 bf16 cols * 2B
            uint32_t aH[4][4], aL[4][4], bH[2][4], bL[2][4];
#pragma unroll
            for (int mt = 0; mt < 4; mt++) {
                ldm_x4(aH[mt], sAhB + aoff + mt * (16*LDT*2) + kso);
                ldm_x4(aL[mt], sAlB + aoff + mt * (16*LDT*2) + kso);
            }
#pragma unroll
            for (int np = 0; np < 2; np++) {
                ldm_x4(bH[np], sBhB + boff + np * (16*LDT*2) + kso);
                ldm_x4(bL[np], sBlB + boff + np * (16*LDT*2) + kso);
            }
#pragma unroll
            for (int mt = 0; mt < 4; mt++)
#pragma unroll
                for (int nt = 0; nt < 4; nt++) {
                    const uint32_t* ph = &bH[nt >> 1][(nt & 1) * 2];
                    const uint32_t* pl = &bL[nt >> 1][(nt & 1) * 2];
                    mma16816(acc[mt][nt], aH[mt], ph);
                    mma16816(acc[mt][nt], aH[mt], pl);
                    mma16816(acc[mt][nt], aL[mt], ph);
                }
        }
        __syncthreads();                       // stage stg free for reload
    }

    // Epilogue. C frag: d0,d1 -> row g, cols 2tig,2tig+1; d2,d3 -> row g+8.
    const int g = lane >> 2, tig = lane & 3;
    if (MODE == 0) {
        const int kmat = n0 >> 10;                   // 0=q 1=k 2=v
        float* dst = (kmat == 0) ? g_q : ((kmat == 1) ? g_k : g_v);
#pragma unroll
        for (int mt = 0; mt < 4; mt++)
#pragma unroll
            for (int hh = 0; hh < 2; hh++) {
                const int m = m0 + wm*64 + mt*16 + hh*8 + g;
                const int b = m >> 11, s = m & 2047;
#pragma unroll
                for (int nt = 0; nt < 4; nt++) {
                    const int colg = n0 + wn*32 + nt*8 + 2*tig;
                    const int h = (colg >> 6) & 15;
                    const int cc = colg & 63;
                    const float v0 = acc[mt][nt][hh*2];
                    const float v1 = acc[mt][nt][hh*2 + 1];
                    float2 r;
                    if (kmat < 2) {
                        const int pi = (s << 5) + (cc >> 1);
                        const float c_ = g_cos[pi], s_ = g_sin[pi];
                        r.x = v0 * c_ - v1 * s_;
                        r.y = v0 * s_ + v1 * c_;
                    } else {
                        r.x = v0; r.y = v1;
                    }
                    *(float2*)(dst + ((size_t)((b*PH + h)*PS + s))*PDH + cc) = r;
                }
            }
    } else {
#pragma unroll
        for (int mt = 0; mt < 4; mt++)
#pragma unroll
            for (int hh = 0; hh < 2; hh++) {
                const int m = m0 + wm*64 + mt*16 + hh*8 + g;
#pragma unroll
                for (int nt = 0; nt < 4; nt++) {
                    const int colg = n0 + wn*32 + nt*8 + 2*tig;
                    float2 r;
                    r.x = acc[mt][nt][hh*2];
                    r.y = acc[mt][nt][hh*2 + 1];
                    *(float2*)(Cout + (size_t)m * 1024 + colg) = r;
                }
            }
    }
}

// ---------------------------------------------------------------------------
// Flash attention, fp32 (unchanged from passing round)
// ---------------------------------------------------------------------------
__global__ __launch_bounds__(256) void flash_attn_kernel() {
    extern __shared__ float sm[];
    float* Qs = sm;                  // 64*68
    float* Ks = sm + 64 * 68;        // 64*68
    float* Vs = Ks + 64 * 68;        // 64*64
    float* Ps = Vs + 64 * 64;        // 64*68

    const int tid = threadIdx.x;
    const int tx = tid & 15;
    const int ty = tid >> 4;
    const int qb = blockIdx.x;
    const int bh = blockIdx.y;

    const float* Qg  = g_q + ((size_t)bh * PS + qb * 64) * PDH;
    const float* Kg0 = g_k + (size_t)bh * PS * PDH;
    const float* Vg0 = g_v + (size_t)bh * PS * PDH;

    {
        int row = tid & 63;
        int c4b = tid >> 6;
        float4 t[4];
#pragma unroll
        for (int p = 0; p < 4; p++) {
            int c4 = c4b + p * 4;
            t[p] = *(const float4*)(Qg + row * 64 + c4 * 4);
        }
#pragma unroll
        for (int p = 0; p < 4; p++) {
            int c4 = c4b + p * 4;
            Qs[(c4*4+0)*68 + row] = t[p].x;
            Qs[(c4*4+1)*68 + row] = t[p].y;
            Qs[(c4*4+2)*68 + row] = t[p].z;
            Qs[(c4*4+3)*68 + row] = t[p].w;
        }
    }

    float o[4][4];
    float mrow[4], lrow[4];
#pragma unroll
    for (int i = 0; i < 4; i++) {
        mrow[i] = -1e30f; lrow[i] = 0.0f;
#pragma unroll
        for (int j = 0; j < 4; j++) o[i][j] = 0.0f;
    }

    for (int j = 0; j <= qb; j++) {
        const float* Kg = Kg0 + j * 64 * 64;
        const float* Vg = Vg0 + j * 64 * 64;
        int row = tid & 63;
        int c4b = tid >> 6;
        float4 kt[4], vt[4];
#pragma unroll
        for (int p = 0; p < 4; p++) {
            int c4 = c4b + p * 4;
            kt[p] = *(const float4*)(Kg + row * 64 + c4 * 4);
            int f = tid + 256 * p;
            vt[p] = *(const float4*)(Vg + (f >> 4) * 64 + (f & 15) * 4);
        }
        __syncthreads();
#pragma unroll
        for (int p = 0; p < 4; p++) {
            int c4 = c4b + p * 4;
            Ks[(c4*4+0)*68 + row] = kt[p].x;
            Ks[(c4*4+1)*68 + row] = kt[p].y;
            Ks[(c4*4+2)*68 + row] = kt[p].z;
            Ks[(c4*4+3)*68 + row] = kt[p].w;
            int f = tid + 256 * p;
            *(float4*)&Vs[(f >> 4) * 64 + (f & 15) * 4] = vt[p];
        }
        __syncthreads();

        float sc[4][4];
#pragma unroll
        for (int i = 0; i < 4; i++)
#pragma unroll
            for (int jj = 0; jj < 4; jj++) sc[i][jj] = 0.0f;
#pragma unroll 8
        for (int d = 0; d < 64; d++) {
            float4 q4 = *(const float4*)&Qs[d * 68 + ty * 4];
            float4 k4 = *(const float4*)&Ks[d * 68 + tx * 4];
            float qa[4] = {q4.x, q4.y, q4.z, q4.w};
            float ka[4] = {k4.x, k4.y, k4.z, k4.w};
#pragma unroll
            for (int i = 0; i < 4; i++)
#pragma unroll
                for (int jj = 0; jj < 4; jj++) sc[i][jj] += qa[i] * ka[jj];
        }
        if (j == qb) {
#pragma unroll
            for (int i = 0; i < 4; i++) {
                int qg = qb * 64 + ty * 4 + i;
#pragma unroll
                for (int jj = 0; jj < 4; jj++) {
                    int kg = j * 64 + tx * 4 + jj;
                    sc[i][jj] = (kg > qg) ? -1e30f : sc[i][jj] * 0.125f;
                }
            }
        } else {
#pragma unroll
            for (int i = 0; i < 4; i++)
#pragma unroll
                for (int jj = 0; jj < 4; jj++) sc[i][jj] *= 0.125f;
        }

#pragma unroll
        for (int i = 0; i < 4; i++) {
            float rm = fmaxf(fmaxf(sc[i][0], sc[i][1]), fmaxf(sc[i][2], sc[i][3]));
#pragma unroll
            for (int off = 8; off >= 1; off >>= 1)
                rm = fmaxf(rm, __shfl_xor_sync(0xffffffffu, rm, off));
            float mnew = fmaxf(mrow[i], rm);
            float alpha = __expf(mrow[i] - mnew);
            float ps = 0.0f;
#pragma unroll
            for (int jj = 0; jj < 4; jj++) {
                sc[i][jj] = __expf(sc[i][jj] - mnew);
                ps += sc[i][jj];
            }
#pragma unroll
            for (int off = 8; off >= 1; off >>= 1)
                ps += __shfl_xor_sync(0xffffffffu, ps, off);
            lrow[i] = lrow[i] * alpha + ps;
            mrow[i] = mnew;
#pragma unroll
            for (int jj = 0; jj < 4; jj++) o[i][jj] *= alpha;
        }

#pragma unroll
        for (int i = 0; i < 4; i++) {
            float4 pv;
            pv.x = sc[i][0]; pv.y = sc[i][1]; pv.z = sc[i][2]; pv.w = sc[i][3];
            *(float4*)&Ps[(ty * 4 + i) * 68 + tx * 4] = pv;
        }
        __syncthreads();

#pragma unroll 4
        for (int k2 = 0; k2 < 64; k2++) {
            float4 v4 = *(const float4*)&Vs[k2 * 64 + tx * 4];
            float va[4] = {v4.x, v4.y, v4.z, v4.w};
#pragma unroll
            for (int i = 0; i < 4; i++) {
                float p = Ps[(ty * 4 + i) * 68 + k2];
#pragma unroll
                for (int jj = 0; jj < 4; jj++) o[i][jj] += p * va[jj];
            }
        }
    }

    int b = bh >> 4, h = bh & 15;
#pragma unroll
    for (int i = 0; i < 4; i++) {
        int sgl = qb * 64 + ty * 4 + i;
        float inv = 1.0f / lrow[i];
        float4 r;
        r.x = o[i][0] * inv; r.y = o[i][1] * inv;
        r.z = o[i][2] * inv; r.w = o[i][3] * inv;
        *(float4*)(g_attn + ((size_t)(b * PS + sgl) * PD) + h * 64 + tx * 4) = r;
    }
}

// ---------------------------------------------------------------------------
extern "C" void kernel_launch(void* const* d_in, const int* in_sizes, int n_in,
                              void* d_out, int out_size) {
    const float* x     = (const float*)d_in[0];
    const float* W_qkv = (const float*)d_in[1];
    const float* W_o   = (const float*)d_in[2];
    const int*   tpos  = (const int*)d_in[3];
    float* out = (float*)d_out;

    static const size_t FLASH_SMEM = (size_t)(64*68*2 + 64*64 + 64*68) * sizeof(float);
    cudaFuncSetAttribute(flash_attn_kernel,
                         cudaFuncAttributeMaxDynamicSharedMemorySize, (int)FLASH_SMEM);
    cudaFuncSetAttribute(mma_gemm_kernel<0>,
                         cudaFuncAttributeMaxDynamicSharedMemorySize, GEMM_SMEM);
    cudaFuncSetAttribute(mma_gemm_kernel<1>,
                         cudaFuncAttributeMaxDynamicSharedMemorySize, GEMM_SMEM);

    rope_table_kernel<<<64, 1024>>>(tpos);
    split_x_kernel<<<8192, 256>>>(x);
    split_wq_kernel<<<3072, 256>>>(W_qkv);
    split_wo_kernel<<<1024, 256>>>(W_o);

    mma_gemm_kernel<0><<<dim3(24, 64), 256, GEMM_SMEM>>>(nullptr);   // QKV + RoPE
    flash_attn_kernel<<<dim3(32, 64), 256, FLASH_SMEM>>>();
    split_attn_kernel<<<8192, 256>>>();
    mma_gemm_kernel<1><<<dim3(8, 64), 256, GEMM_SMEM>>>(out);        // out proj
}